// round 12
// baseline (speedup 1.0000x reference)
#include <cuda_runtime.h>
#include <cuda_bf16.h>
#include <cstdint>
#include <cstddef>

// ============================================================================
// CausalAttentionLayer, split-kernel design (HMMA mma.sync; tcgen05 is
// feature-gated off because harness PTX targets sm_103 without the 'a').
//
//   S = Q K^T (no scaling); P = softmax(S, FULL row) * strict-lower mask;
//   O = P V.
// Fixed exp shift (40) => no online softmax: P tiles and row denominators are
// computable independently, so S-phase and PV-phase are separate balanced
// GEMM kernels linked by a P-fragment scratch buffer.
//
// Round-12 deltas:
//  * s_kernel: split-K (Kh/Kl) software pipeline — pass1 (Qh*Kh + Ql*Kh)
//    overlaps the Kl(kt) load; pass2 (Qh*Kl) + softmax overlap the Kh(kt+1)
//    load. K-wait exposure ~0. Always-commit keeps cp.async FIFO uniform.
//  * pv_kernel: 64-key V chunks, double-buffered, 6 CTAs/SM (24 warps/SM).
// ============================================================================

#define BATCH 32
#define NSEQ  1024
#define CD    128
#define CMD   256
#define NKT   8
#define SHIFT 40.0f

#define SQ    136                    // s_kernel smem row stride (bf16)

// ---- s_kernel smem ----
#define S_OQH 0                      // Q hi: 64 x 128 -> 64*136*2 = 17408
#define S_OQL 17408
#define S_OKH 34816                  // K hi: 128 x 128 -> 34816
#define S_OKL 69632
#define S_ODS 104448                 // denom staging: 128 floats
#define S_SMEM (104448 + 512)

// ---- pv_kernel smem: 2 buffers, each Vh+Vl of a 64cm x 64key chunk ----
#define PVS    72                    // pv smem row stride (bf16)
#define PV_MAT (64 * PVS * 2)        // 9216 B per matrix
#define PV_BUF (2 * PV_MAT)          // 18432 B (Vh + Vl)
#define PV_SMEM (2 * PV_BUF)         // 36864 B

// ---------------- scratch ----------------
__device__ uint4 g_Qh[BATCH*NSEQ*CD/8];
__device__ uint4 g_Ql[BATCH*NSEQ*CD/8];
__device__ uint4 g_Kh[BATCH*NSEQ*CD/8];
__device__ uint4 g_Kl[BATCH*NSEQ*CD/8];
__device__ uint4 g_Vth[BATCH*CMD*NSEQ/8];
__device__ uint4 g_Vtl[BATCH*CMD*NSEQ/8];
// P fragments: [b][qx 16][kt 8][rg 4][s 8][lane 32] -> uint4 (a0..a3)
__device__ uint4 g_Ph[BATCH*16*8*4*8*32];
__device__ uint4 g_Pl[BATCH*16*8*4*8*32];
__device__ float g_d[BATCH*NSEQ];

// ---------------- helpers ----------------
static __device__ __forceinline__ uint32_t smem_u32(const void* p) {
    uint32_t a;
    asm("{ .reg .u64 t; cvta.to.shared.u64 t, %1; cvt.u32.u64 %0, t; }"
        : "=r"(a) : "l"(p));
    return a;
}

static __device__ __forceinline__ void ldsm4(uint32_t r[4], uint32_t addr) {
    asm volatile("ldmatrix.sync.aligned.m8n8.x4.shared.b16 {%0,%1,%2,%3}, [%4];"
                 : "=r"(r[0]), "=r"(r[1]), "=r"(r[2]), "=r"(r[3]) : "r"(addr));
}

static __device__ __forceinline__ void mma16816(float c[4],
                                                uint32_t a0, uint32_t a1,
                                                uint32_t a2, uint32_t a3,
                                                uint32_t b0, uint32_t b1) {
    asm volatile(
        "mma.sync.aligned.m16n8k16.row.col.f32.bf16.bf16.f32 "
        "{%0,%1,%2,%3}, {%4,%5,%6,%7}, {%8,%9}, {%0,%1,%2,%3};"
        : "+f"(c[0]), "+f"(c[1]), "+f"(c[2]), "+f"(c[3])
        : "r"(a0), "r"(a1), "r"(a2), "r"(a3), "r"(b0), "r"(b1));
}

static __device__ __forceinline__ uint32_t pack2(float a, float b) {
    __nv_bfloat162 t = __floats2bfloat162_rn(a, b);
    uint32_t r;
    memcpy(&r, &t, 4);
    return r;
}

static __device__ __forceinline__ void cpa16(uint32_t dst, const void* src) {
    asm volatile("cp.async.cg.shared.global [%0], [%1], 16;"
                 :: "r"(dst), "l"(src));
}
#define CP_COMMIT() asm volatile("cp.async.commit_group;" ::: "memory")
#define CP_WAIT(n)  asm volatile("cp.async.wait_group %0;" :: "n"(n) : "memory")

// ---------------- kernel 1: fused prep (hi/lo split + V transpose) ----------
__global__ void prep_all(const float* __restrict__ q, const float* __restrict__ k,
                         const float* __restrict__ v) {
    __shared__ float t[32][33];
    const int bid = blockIdx.x, tid = threadIdx.x;
    if (bid < 4096) {
        int i = bid * 256 + tid;
        float4 a = ((const float4*)q)[i];
        float4 bb = ((const float4*)k)[i];
        float hx, hy, hz, hw;
        uint2 h, l;
        hx = __bfloat162float(__float2bfloat16(a.x));
        hy = __bfloat162float(__float2bfloat16(a.y));
        hz = __bfloat162float(__float2bfloat16(a.z));
        hw = __bfloat162float(__float2bfloat16(a.w));
        h.x = pack2(hx, hy); h.y = pack2(hz, hw);
        l.x = pack2(a.x - hx, a.y - hy); l.y = pack2(a.z - hz, a.w - hw);
        ((uint2*)g_Qh)[i] = h; ((uint2*)g_Ql)[i] = l;
        hx = __bfloat162float(__float2bfloat16(bb.x));
        hy = __bfloat162float(__float2bfloat16(bb.y));
        hz = __bfloat162float(__float2bfloat16(bb.z));
        hw = __bfloat162float(__float2bfloat16(bb.w));
        h.x = pack2(hx, hy); h.y = pack2(hz, hw);
        l.x = pack2(bb.x - hx, bb.y - hy); l.y = pack2(bb.z - hz, bb.w - hw);
        ((uint2*)g_Kh)[i] = h; ((uint2*)g_Kl)[i] = l;
    } else {
        int vb = bid - 4096;                 // 0..8191
        int b  = vb >> 8;
        int c0 = ((vb >> 5) & 7) * 32;
        int k0 = (vb & 31) * 32;
        int tx = tid & 31, ty = tid >> 5;    // (32, 8)
        #pragma unroll
        for (int r = 0; r < 4; r++)
            t[ty + 8 * r][tx] =
                v[((size_t)b * NSEQ + k0 + ty + 8 * r) * CMD + c0 + tx];
        __syncthreads();
        __nv_bfloat16* oh = (__nv_bfloat16*)g_Vth;
        __nv_bfloat16* ol = (__nv_bfloat16*)g_Vtl;
        #pragma unroll
        for (int r = 0; r < 4; r++) {
            float x = t[tx][ty + 8 * r];
            __nv_bfloat16 hh = __float2bfloat16(x);
            size_t o = ((size_t)b * CMD + c0 + ty + 8 * r) * NSEQ + k0 + tx;
            oh[o] = hh;
            ol[o] = __float2bfloat16(x - __bfloat162float(hh));
        }
    }
}

// ---------------- kernel 2: S + softmax -> P fragments + denominators -------
__global__ __launch_bounds__(256, 2)
void s_kernel() {
    extern __shared__ uint8_t sm[];
    const uint32_t smb = smem_u32(sm);
    const int tid  = threadIdx.x;
    const int warp = tid >> 5, lane = tid & 31;
    const int rg   = warp & 3;            // row group: rows rg*16..+15
    const int kh   = warp >> 2;           // key half: keys kh*64..+63
    const int g    = lane >> 2, t = lane & 3;
    const int qx   = blockIdx.x;          // 64-row q tile 0..15
    const int b    = blockIdx.y;
    const int q0   = qx * 64;

    const __nv_bfloat16* pQh = (const __nv_bfloat16*)g_Qh;
    const __nv_bfloat16* pQl = (const __nv_bfloat16*)g_Ql;
    const __nv_bfloat16* pKh = (const __nv_bfloat16*)g_Kh;
    const __nv_bfloat16* pKl = (const __nv_bfloat16*)g_Kl;

    // ---- prologue: group0 = Q(hi+lo) + Kh(0); group1 = Kl(0) ----
    {
        const __nv_bfloat16* sQh = pQh + ((size_t)b * NSEQ + q0) * CD;
        const __nv_bfloat16* sQl = pQl + ((size_t)b * NSEQ + q0) * CD;
        #pragma unroll
        for (int it = 0; it < 4; it++) {
            int c = tid + it * 256;       // 1024 granules
            int r = c >> 4, c8 = c & 15;
            cpa16(smb + S_OQH + ((uint32_t)r * SQ + c8 * 8) * 2, sQh + (size_t)r * CD + c8 * 8);
            cpa16(smb + S_OQL + ((uint32_t)r * SQ + c8 * 8) * 2, sQl + (size_t)r * CD + c8 * 8);
        }
        const __nv_bfloat16* sKh = pKh + (size_t)b * NSEQ * CD;
        #pragma unroll
        for (int it = 0; it < 8; it++) {
            int c = tid + it * 256;       // 2048 granules
            int r = c >> 4, c8 = c & 15;
            cpa16(smb + S_OKH + ((uint32_t)r * SQ + c8 * 8) * 2, sKh + (size_t)r * CD + c8 * 8);
        }
    }
    CP_COMMIT();
    {
        const __nv_bfloat16* sKl = pKl + (size_t)b * NSEQ * CD;
        #pragma unroll
        for (int it = 0; it < 8; it++) {
            int c = tid + it * 256;
            int r = c >> 4, c8 = c & 15;
            cpa16(smb + S_OKL + ((uint32_t)r * SQ + c8 * 8) * 2, sKl + (size_t)r * CD + c8 * 8);
        }
    }
    CP_COMMIT();

    // ldmatrix addresses
    const uint32_t aQrow = rg * 16 + (lane & 15);
    const uint32_t aQkof = (lane >> 4) * 8;
    const uint32_t aQh0 = smb + S_OQH + (aQrow * SQ + aQkof) * 2;
    const uint32_t aQl0 = smb + S_OQL + (aQrow * SQ + aQkof) * 2;
    const uint32_t bn  = (lane & 7) + ((lane >= 16) ? 8 : 0);
    const uint32_t bk  = (lane & 8) ? 8 : 0;
    const uint32_t aKh0 = smb + S_OKH + (((uint32_t)kh * 64 + bn) * SQ + bk) * 2;
    const uint32_t aKl0 = smb + S_OKL + (((uint32_t)kh * 64 + bn) * SQ + bk) * 2;

    const int row0 = q0 + rg * 16 + g;
    const int row1 = row0 + 8;
    float d0 = 0.0f, d1 = 0.0f;
    const int ktmax_store = qx >> 1;      // causal tiles: kt <= qx>>1

    for (int kt = 0; kt < NKT; kt++) {
        float Sc[8][4];
        #pragma unroll
        for (int u = 0; u < 8; u++)
            #pragma unroll
            for (int x = 0; x < 4; x++) Sc[u][x] = 0.0f;

        // ---- pass1: Qh*Kh + Ql*Kh (Kl(kt) still streaming in) ----
        CP_WAIT(1);                       // Kh(kt) (FIFO-oldest) landed
        __syncthreads();
        for (int s = 0; s < 8; s++) {
            uint32_t Ah[4], Al[4];
            ldsm4(Ah, aQh0 + s * 32);
            ldsm4(Al, aQl0 + s * 32);
            #pragma unroll
            for (int u = 0; u < 4; u++) {
                uint32_t Bh[4];
                ldsm4(Bh, aKh0 + (uint32_t)u * (16 * SQ * 2) + s * 32);
                mma16816(Sc[2*u],   Ah[0],Ah[1],Ah[2],Ah[3], Bh[0],Bh[1]);
                mma16816(Sc[2*u],   Al[0],Al[1],Al[2],Al[3], Bh[0],Bh[1]);
                mma16816(Sc[2*u+1], Ah[0],Ah[1],Ah[2],Ah[3], Bh[2],Bh[3]);
                mma16816(Sc[2*u+1], Al[0],Al[1],Al[2],Al[3], Bh[2],Bh[3]);
            }
        }
        __syncthreads();                  // Kh buffer free

        // ---- prefetch Kh(kt+1) (empty commit on last tile) ----
        if (kt < NKT - 1) {
            const __nv_bfloat16* sKh = pKh + ((size_t)b * NSEQ + (kt + 1) * 128) * CD;
            #pragma unroll
            for (int it = 0; it < 8; it++) {
                int c = tid + it * 256;
                int r = c >> 4, c8 = c & 15;
                cpa16(smb + S_OKH + ((uint32_t)r * SQ + c8 * 8) * 2, sKh + (size_t)r * CD + c8 * 8);
            }
        }
        CP_COMMIT();

        // ---- pass2: Qh*Kl (Kh(kt+1) streaming in) ----
        CP_WAIT(1);                       // Kl(kt) landed
        __syncthreads();
        for (int s = 0; s < 8; s++) {
            uint32_t Ah[4];
            ldsm4(Ah, aQh0 + s * 32);
            #pragma unroll
            for (int u = 0; u < 4; u++) {
                uint32_t Bl[4];
                ldsm4(Bl, aKl0 + (uint32_t)u * (16 * SQ * 2) + s * 32);
                mma16816(Sc[2*u],   Ah[0],Ah[1],Ah[2],Ah[3], Bl[0],Bl[1]);
                mma16816(Sc[2*u+1], Ah[0],Ah[1],Ah[2],Ah[3], Bl[2],Bl[3]);
            }
        }
        __syncthreads();                  // Kl buffer free

        // ---- prefetch Kl(kt+1) (empty commit on last tile) ----
        if (kt < NKT - 1) {
            const __nv_bfloat16* sKl = pKl + ((size_t)b * NSEQ + (kt + 1) * 128) * CD;
            #pragma unroll
            for (int it = 0; it < 8; it++) {
                int c = tid + it * 256;
                int r = c >> 4, c8 = c & 15;
                cpa16(smb + S_OKL + ((uint32_t)r * SQ + c8 * 8) * 2, sKl + (size_t)r * CD + c8 * 8);
            }
        }
        CP_COMMIT();

        // ---- exp, denominators, masked P fragments -> gmem ----
        const bool store_p = (kt <= ktmax_store);
        #pragma unroll
        for (int u = 0; u < 4; u++) {
            const int cA = kt * 128 + kh * 64 + u * 16 + 2 * t;
            const int cB = cA + 8;
            float e00 = __expf(Sc[2*u][0] - SHIFT), e01 = __expf(Sc[2*u][1] - SHIFT);
            float e02 = __expf(Sc[2*u][2] - SHIFT), e03 = __expf(Sc[2*u][3] - SHIFT);
            float f00 = __expf(Sc[2*u+1][0] - SHIFT), f01 = __expf(Sc[2*u+1][1] - SHIFT);
            float f02 = __expf(Sc[2*u+1][2] - SHIFT), f03 = __expf(Sc[2*u+1][3] - SHIFT);
            d0 += (e00 + e01) + (f00 + f01);
            d1 += (e02 + e03) + (f02 + f03);
            if (store_p) {
                float p00 = (cA     < row0) ? e00 : 0.0f;
                float p01 = (cA + 1 < row0) ? e01 : 0.0f;
                float p02 = (cA     < row1) ? e02 : 0.0f;
                float p03 = (cA + 1 < row1) ? e03 : 0.0f;
                float q00 = (cB     < row0) ? f00 : 0.0f;
                float q01 = (cB + 1 < row0) ? f01 : 0.0f;
                float q02 = (cB     < row1) ? f02 : 0.0f;
                float q03 = (cB + 1 < row1) ? f03 : 0.0f;
                float h00 = __bfloat162float(__float2bfloat16(p00));
                float h01 = __bfloat162float(__float2bfloat16(p01));
                float h02 = __bfloat162float(__float2bfloat16(p02));
                float h03 = __bfloat162float(__float2bfloat16(p03));
                float i00 = __bfloat162float(__float2bfloat16(q00));
                float i01 = __bfloat162float(__float2bfloat16(q01));
                float i02 = __bfloat162float(__float2bfloat16(q02));
                float i03 = __bfloat162float(__float2bfloat16(q03));
                // fragment index: [b][qx][kt][rg][s = kh*4+u][lane]
                size_t fi = ((((((size_t)b * 16 + qx) * 8 + kt) * 4 + rg) * 8
                              + (kh * 4 + u)) * 32) + lane;
                g_Ph[fi] = make_uint4(pack2(h00, h01), pack2(h02, h03),
                                      pack2(i00, i01), pack2(i02, i03));
                g_Pl[fi] = make_uint4(pack2(p00 - h00, p01 - h01),
                                      pack2(p02 - h02, p03 - h03),
                                      pack2(q00 - i00, q01 - i01),
                                      pack2(q02 - i02, q03 - i03));
            }
        }
    }

    // ---- denominators: quad reduce, cross-key-half combine, store ----
    d0 += __shfl_xor_sync(0xffffffffu, d0, 1);
    d0 += __shfl_xor_sync(0xffffffffu, d0, 2);
    d1 += __shfl_xor_sync(0xffffffffu, d1, 1);
    d1 += __shfl_xor_sync(0xffffffffu, d1, 2);
    float* dsm = (float*)(sm + S_ODS);
    if (t == 0) {
        dsm[kh * 64 + rg * 16 + g]     = d0;
        dsm[kh * 64 + rg * 16 + g + 8] = d1;
    }
    __syncthreads();
    if (tid < 64)
        g_d[(size_t)b * NSEQ + q0 + tid] = dsm[tid] + dsm[64 + tid];
}

// ---------------- kernel 3: O = P V (pure GEMM, 64-key chunks) --------------
__global__ __launch_bounds__(128, 6)
void pv_kernel(float* __restrict__ outg) {
    extern __shared__ uint8_t sm[];
    const uint32_t smb = smem_u32(sm);
    const int tid  = threadIdx.x;
    const int rg   = tid >> 5, lane = tid & 31;
    const int g    = lane >> 2, t = lane & 3;

    // LPT decode: big qx first
    const int bid = blockIdx.x;                    // 0..2047
    const int qx  = 15 - (bid >> 7);
    const int r   = bid & 127;
    const int cmq = r & 3;                         // 64-cm quarter
    const int b   = r >> 2;
    const int q0  = qx * 64;
    const int nch = ((qx >> 1) + 1) * 2;           // causal 64-key chunks

    const __nv_bfloat16* pVh = (const __nv_bfloat16*)g_Vth;
    const __nv_bfloat16* pVl = (const __nv_bfloat16*)g_Vtl;

    // stage one V chunk (64 cm rows x 64 keys, hi+lo) into buffer c&1
    auto stageV = [&](int c) {
        const __nv_bfloat16* sh = pVh + ((size_t)b * CMD + cmq * 64) * NSEQ + c * 64;
        const __nv_bfloat16* sl = pVl + ((size_t)b * CMD + cmq * 64) * NSEQ + c * 64;
        const uint32_t base = smb + (c & 1) * PV_BUF;
        #pragma unroll
        for (int it = 0; it < 4; it++) {
            int cc = tid + it * 128;               // 512 granules per matrix
            int rr = cc >> 3, c8 = cc & 7;
            cpa16(base + ((uint32_t)rr * PVS + c8 * 8) * 2, sh + (size_t)rr * NSEQ + c8 * 8);
            cpa16(base + PV_MAT + ((uint32_t)rr * PVS + c8 * 8) * 2, sl + (size_t)rr * NSEQ + c8 * 8);
        }
    };

    // V ldsm per-lane base (within buffer): lanes<16 -> Vh, >=16 -> Vl
    const uint32_t vn = lane & 7;
    const uint32_t vk = (lane & 8) ? 8 : 0;
    const uint32_t aVrel = ((lane < 16) ? 0u : (uint32_t)PV_MAT) + (vn * PVS + vk) * 2;

    float O[8][4];
    #pragma unroll
    for (int j = 0; j < 8; j++)
        #pragma unroll
        for (int x = 0; x < 4; x++) O[j][x] = 0.0f;

    const uint4* __restrict__ basePh =
        g_Ph + (((((size_t)b * 16 + qx) * 8) * 4 + rg) * 8) * 32 + lane;
    const uint4* __restrict__ basePl =
        g_Pl + (((((size_t)b * 16 + qx) * 8) * 4 + rg) * 8) * 32 + lane;
    // per-kt stride: 4 rg * 8 s * 32 lanes = 1024 uint4

    stageV(0);
    CP_COMMIT();

    for (int c = 0; c < nch; c++) {
        if (c + 1 < nch) {                         // prefetch next chunk
            stageV(c + 1);
            CP_COMMIT();
            CP_WAIT(1);                            // chunk c (oldest) landed
        } else {
            CP_WAIT(0);
        }
        __syncthreads();                           // chunk c visible everywhere

        const int kt = c >> 1;
        const int s0 = (c & 1) * 4;                // s range within kt
        const uint32_t vbase = smb + (c & 1) * PV_BUF + aVrel;
        const uint4* ph = basePh + (size_t)kt * 1024;
        const uint4* pl = basePl + (size_t)kt * 1024;
        #pragma unroll
        for (int s4 = 0; s4 < 4; s4++) {
            uint4 Ph = ph[(s0 + s4) * 32];         // coalesced LDG.128
            uint4 Pl = pl[(s0 + s4) * 32];
            #pragma unroll
            for (int j = 0; j < 8; j++) {
                uint32_t Bv[4];                    // [0,1]=Vh k0,k8  [2,3]=Vl
                ldsm4(Bv, vbase + (uint32_t)j * (8 * PVS * 2) + s4 * 32);
                mma16816(O[j], Ph.x, Ph.y, Ph.z, Ph.w, Bv[0], Bv[1]);
                mma16816(O[j], Pl.x, Pl.y, Pl.z, Pl.w, Bv[0], Bv[1]);
                mma16816(O[j], Ph.x, Ph.y, Ph.z, Ph.w, Bv[2], Bv[3]);
            }
        }
        __syncthreads();                           // done reading buffer c&1
    }

    // ---- epilogue: divide by full-row denominator, store ----
    const int row0 = q0 + rg * 16 + g;
    const int row1 = row0 + 8;
    const float i0 = 1.0f / g_d[(size_t)b * NSEQ + row0];
    const float i1 = 1.0f / g_d[(size_t)b * NSEQ + row1];
    const size_t r0o = ((size_t)b * NSEQ + row0) * CMD + cmq * 64;
    const size_t r1o = ((size_t)b * NSEQ + row1) * CMD + cmq * 64;
    #pragma unroll
    for (int j = 0; j < 8; j++) {
        float2 v0, v1;
        v0.x = O[j][0] * i0; v0.y = O[j][1] * i0;
        v1.x = O[j][2] * i1; v1.y = O[j][3] * i1;
        *(float2*)(outg + r0o + 8 * j + 2 * t) = v0;
        *(float2*)(outg + r1o + 8 * j + 2 * t) = v1;
    }
}

// ---------------- launch ----------------
extern "C" void kernel_launch(void* const* d_in, const int* in_sizes, int n_in,
                              void* d_out, int out_size)
{
    const float* q = (const float*)d_in[0];
    const float* k = (const float*)d_in[1];
    const float* v = (const float*)d_in[2];
    float* out = (float*)d_out;

    cudaFuncSetAttribute(s_kernel,
                         cudaFuncAttributeMaxDynamicSharedMemorySize, S_SMEM);
    cudaFuncSetAttribute(pv_kernel,
                         cudaFuncAttributeMaxDynamicSharedMemorySize, PV_SMEM);

    prep_all<<<4096 + 8192, 256>>>(q, k, v);
    s_kernel<<<dim3(16, BATCH), 256, S_SMEM>>>();
    pv_kernel<<<2048, 128, PV_SMEM>>>(out);

    (void)in_sizes; (void)n_in; (void)out_size;
}

// round 13
// speedup vs baseline: 1.0366x; 1.0366x over previous
#include <cuda_runtime.h>
#include <cuda_bf16.h>
#include <cstdint>
#include <cstddef>

// ============================================================================
// CausalAttentionLayer, split-kernel design (HMMA mma.sync; tcgen05 is
// feature-gated off because harness PTX targets sm_103 without the 'a').
//
//   S = Q K^T (no scaling); P = softmax(S, FULL row) * strict-lower mask;
//   O = P V.
// Fixed exp shift (40) => no online softmax: P tiles and row denominators are
// computable independently, so S-phase and PV-phase are separate balanced
// GEMM kernels linked by a P-fragment scratch buffer.
//
// Round-13: prep_all + s_kernel reverted to the round-11 (186.4us) versions.
// pv_kernel only: warp tile widened to 32 rows x 64 cm (CTA = cm-HALF, grid
// 1024) so each V fragment is ldsm'd 2x instead of 4x (smem crossbar traffic
// halved), each ldsm feeds 6 mma instead of 3. Sync cadence (192 mma/warp
// between barriers) identical to round-11.
// ============================================================================

#define BATCH 32
#define NSEQ  1024
#define CD    128
#define CMD   256
#define NKT   8
#define SHIFT 40.0f

#define SQ    136                    // s_kernel smem row stride (bf16)

// ---- s_kernel smem ----
#define S_OQH 0                      // Q hi: 64 x 128 -> 64*136*2 = 17408
#define S_OQL 17408
#define S_OKH 34816                  // K hi: 128 x 128 -> 34816
#define S_OKL 69632
#define S_ODS 104448                 // denom staging: 128 floats
#define S_SMEM (104448 + 512)

// ---- pv_kernel smem: 2 buffers, each Vh+Vl of a 128cm x 64key chunk ----
#define PVS    72                    // pv smem row stride (bf16)
#define PV_MAT (128 * PVS * 2)       // 18432 B per matrix (128 cm rows)
#define PV_BUF (2 * PV_MAT)          // 36864 B (Vh + Vl)
#define PV_SMEM (2 * PV_BUF)         // 73728 B -> 3 CTAs/SM

// ---------------- scratch ----------------
__device__ uint4 g_Qh[BATCH*NSEQ*CD/8];
__device__ uint4 g_Ql[BATCH*NSEQ*CD/8];
__device__ uint4 g_Kh[BATCH*NSEQ*CD/8];
__device__ uint4 g_Kl[BATCH*NSEQ*CD/8];
__device__ uint4 g_Vth[BATCH*CMD*NSEQ/8];
__device__ uint4 g_Vtl[BATCH*CMD*NSEQ/8];
// P fragments: [b][qx 16][kt 8][rg 4][s 8][lane 32] -> uint4 (a0..a3)
__device__ uint4 g_Ph[BATCH*16*8*4*8*32];
__device__ uint4 g_Pl[BATCH*16*8*4*8*32];
__device__ float g_d[BATCH*NSEQ];

// ---------------- helpers ----------------
static __device__ __forceinline__ uint32_t smem_u32(const void* p) {
    uint32_t a;
    asm("{ .reg .u64 t; cvta.to.shared.u64 t, %1; cvt.u32.u64 %0, t; }"
        : "=r"(a) : "l"(p));
    return a;
}

static __device__ __forceinline__ void ldsm4(uint32_t r[4], uint32_t addr) {
    asm volatile("ldmatrix.sync.aligned.m8n8.x4.shared.b16 {%0,%1,%2,%3}, [%4];"
                 : "=r"(r[0]), "=r"(r[1]), "=r"(r[2]), "=r"(r[3]) : "r"(addr));
}

static __device__ __forceinline__ void mma16816(float c[4],
                                                uint32_t a0, uint32_t a1,
                                                uint32_t a2, uint32_t a3,
                                                uint32_t b0, uint32_t b1) {
    asm volatile(
        "mma.sync.aligned.m16n8k16.row.col.f32.bf16.bf16.f32 "
        "{%0,%1,%2,%3}, {%4,%5,%6,%7}, {%8,%9}, {%0,%1,%2,%3};"
        : "+f"(c[0]), "+f"(c[1]), "+f"(c[2]), "+f"(c[3])
        : "r"(a0), "r"(a1), "r"(a2), "r"(a3), "r"(b0), "r"(b1));
}

static __device__ __forceinline__ uint32_t pack2(float a, float b) {
    __nv_bfloat162 t = __floats2bfloat162_rn(a, b);
    uint32_t r;
    memcpy(&r, &t, 4);
    return r;
}

static __device__ __forceinline__ void cpa16(uint32_t dst, const void* src) {
    asm volatile("cp.async.cg.shared.global [%0], [%1], 16;"
                 :: "r"(dst), "l"(src));
}
#define CP_COMMIT() asm volatile("cp.async.commit_group;" ::: "memory")
#define CP_WAIT(n)  asm volatile("cp.async.wait_group %0;" :: "n"(n) : "memory")

// ---------------- kernel 1: fused prep (hi/lo split + V transpose) ----------
__global__ void prep_all(const float* __restrict__ q, const float* __restrict__ k,
                         const float* __restrict__ v) {
    __shared__ float t[32][33];
    const int bid = blockIdx.x, tid = threadIdx.x;
    if (bid < 4096) {
        int i = bid * 256 + tid;
        float4 a = ((const float4*)q)[i];
        float4 bb = ((const float4*)k)[i];
        float hx, hy, hz, hw;
        uint2 h, l;
        hx = __bfloat162float(__float2bfloat16(a.x));
        hy = __bfloat162float(__float2bfloat16(a.y));
        hz = __bfloat162float(__float2bfloat16(a.z));
        hw = __bfloat162float(__float2bfloat16(a.w));
        h.x = pack2(hx, hy); h.y = pack2(hz, hw);
        l.x = pack2(a.x - hx, a.y - hy); l.y = pack2(a.z - hz, a.w - hw);
        ((uint2*)g_Qh)[i] = h; ((uint2*)g_Ql)[i] = l;
        hx = __bfloat162float(__float2bfloat16(bb.x));
        hy = __bfloat162float(__float2bfloat16(bb.y));
        hz = __bfloat162float(__float2bfloat16(bb.z));
        hw = __bfloat162float(__float2bfloat16(bb.w));
        h.x = pack2(hx, hy); h.y = pack2(hz, hw);
        l.x = pack2(bb.x - hx, bb.y - hy); l.y = pack2(bb.z - hz, bb.w - hw);
        ((uint2*)g_Kh)[i] = h; ((uint2*)g_Kl)[i] = l;
    } else {
        int vb = bid - 4096;                 // 0..8191
        int b  = vb >> 8;
        int c0 = ((vb >> 5) & 7) * 32;
        int k0 = (vb & 31) * 32;
        int tx = tid & 31, ty = tid >> 5;    // (32, 8)
        #pragma unroll
        for (int r = 0; r < 4; r++)
            t[ty + 8 * r][tx] =
                v[((size_t)b * NSEQ + k0 + ty + 8 * r) * CMD + c0 + tx];
        __syncthreads();
        __nv_bfloat16* oh = (__nv_bfloat16*)g_Vth;
        __nv_bfloat16* ol = (__nv_bfloat16*)g_Vtl;
        #pragma unroll
        for (int r = 0; r < 4; r++) {
            float x = t[tx][ty + 8 * r];
            __nv_bfloat16 hh = __float2bfloat16(x);
            size_t o = ((size_t)b * CMD + c0 + ty + 8 * r) * NSEQ + k0 + tx;
            oh[o] = hh;
            ol[o] = __float2bfloat16(x - __bfloat162float(hh));
        }
    }
}

// ---------------- kernel 2: S + softmax -> P fragments + denominators -------
// (round-11 version, verbatim)
__global__ __launch_bounds__(256, 2)
void s_kernel() {
    extern __shared__ uint8_t sm[];
    const uint32_t smb = smem_u32(sm);
    const int tid  = threadIdx.x;
    const int warp = tid >> 5, lane = tid & 31;
    const int rg   = warp & 3;            // row group: rows rg*16..+15
    const int kh   = warp >> 2;           // key half: keys kh*64..+63
    const int g    = lane >> 2, t = lane & 3;
    const int qx   = blockIdx.x;          // 64-row q tile 0..15
    const int b    = blockIdx.y;
    const int q0   = qx * 64;

    const __nv_bfloat16* pQh = (const __nv_bfloat16*)g_Qh;
    const __nv_bfloat16* pQl = (const __nv_bfloat16*)g_Ql;
    const __nv_bfloat16* pKh = (const __nv_bfloat16*)g_Kh;
    const __nv_bfloat16* pKl = (const __nv_bfloat16*)g_Kl;

    // ---- stage Q (64 rows) + K(0) (128 rows) ----
    {
        const __nv_bfloat16* sQh = pQh + ((size_t)b * NSEQ + q0) * CD;
        const __nv_bfloat16* sQl = pQl + ((size_t)b * NSEQ + q0) * CD;
        #pragma unroll
        for (int it = 0; it < 4; it++) {
            int c = tid + it * 256;       // 1024 granules
            int r = c >> 4, c8 = c & 15;
            cpa16(smb + S_OQH + ((uint32_t)r * SQ + c8 * 8) * 2, sQh + (size_t)r * CD + c8 * 8);
            cpa16(smb + S_OQL + ((uint32_t)r * SQ + c8 * 8) * 2, sQl + (size_t)r * CD + c8 * 8);
        }
        const __nv_bfloat16* sKh = pKh + (size_t)b * NSEQ * CD;
        const __nv_bfloat16* sKl = pKl + (size_t)b * NSEQ * CD;
        #pragma unroll
        for (int it = 0; it < 8; it++) {
            int c = tid + it * 256;       // 2048 granules
            int r = c >> 4, c8 = c & 15;
            cpa16(smb + S_OKH + ((uint32_t)r * SQ + c8 * 8) * 2, sKh + (size_t)r * CD + c8 * 8);
            cpa16(smb + S_OKL + ((uint32_t)r * SQ + c8 * 8) * 2, sKl + (size_t)r * CD + c8 * 8);
        }
    }
    CP_COMMIT();
    CP_WAIT(0);
    __syncthreads();

    // ldmatrix addresses
    const uint32_t aQrow = rg * 16 + (lane & 15);
    const uint32_t aQkof = (lane >> 4) * 8;
    const uint32_t aQh0 = smb + S_OQH + (aQrow * SQ + aQkof) * 2;
    const uint32_t aQl0 = smb + S_OQL + (aQrow * SQ + aQkof) * 2;
    const uint32_t bn  = (lane & 7) + ((lane >= 16) ? 8 : 0);
    const uint32_t bk  = (lane & 8) ? 8 : 0;
    const uint32_t aKh0 = smb + S_OKH + (((uint32_t)kh * 64 + bn) * SQ + bk) * 2;
    const uint32_t aKl0 = smb + S_OKL + (((uint32_t)kh * 64 + bn) * SQ + bk) * 2;

    const int row0 = q0 + rg * 16 + g;
    const int row1 = row0 + 8;
    float d0 = 0.0f, d1 = 0.0f;
    const int ktmax_store = qx >> 1;      // causal tiles: kt <= qx>>1

    for (int kt = 0; kt < NKT; kt++) {
        // ---- S = Qh*Kh + Qh*Kl + Ql*Kh : 16 rows x 64 keys per warp ----
        float Sc[8][4];
        #pragma unroll
        for (int u = 0; u < 8; u++)
            #pragma unroll
            for (int x = 0; x < 4; x++) Sc[u][x] = 0.0f;

        for (int s = 0; s < 8; s++) {
            uint32_t Ah[4], Al[4];
            ldsm4(Ah, aQh0 + s * 32);
            ldsm4(Al, aQl0 + s * 32);
            #pragma unroll
            for (int u = 0; u < 4; u++) {
                uint32_t Bh[4], Bl[4];
                uint32_t off = (uint32_t)u * (16 * SQ * 2) + s * 32;
                ldsm4(Bh, aKh0 + off);
                ldsm4(Bl, aKl0 + off);
                mma16816(Sc[2*u],   Ah[0],Ah[1],Ah[2],Ah[3], Bh[0],Bh[1]);
                mma16816(Sc[2*u],   Ah[0],Ah[1],Ah[2],Ah[3], Bl[0],Bl[1]);
                mma16816(Sc[2*u],   Al[0],Al[1],Al[2],Al[3], Bh[0],Bh[1]);
                mma16816(Sc[2*u+1], Ah[0],Ah[1],Ah[2],Ah[3], Bh[2],Bh[3]);
                mma16816(Sc[2*u+1], Ah[0],Ah[1],Ah[2],Ah[3], Bl[2],Bl[3]);
                mma16816(Sc[2*u+1], Al[0],Al[1],Al[2],Al[3], Bh[2],Bh[3]);
            }
        }
        __syncthreads();                  // all warps done reading K(kt)

        // ---- prefetch K(kt+1); lands while softmax/store runs ----
        if (kt < NKT - 1) {
            const __nv_bfloat16* sKh = pKh + ((size_t)b * NSEQ + (kt + 1) * 128) * CD;
            const __nv_bfloat16* sKl = pKl + ((size_t)b * NSEQ + (kt + 1) * 128) * CD;
            #pragma unroll
            for (int it = 0; it < 8; it++) {
                int c = tid + it * 256;
                int r = c >> 4, c8 = c & 15;
                cpa16(smb + S_OKH + ((uint32_t)r * SQ + c8 * 8) * 2, sKh + (size_t)r * CD + c8 * 8);
                cpa16(smb + S_OKL + ((uint32_t)r * SQ + c8 * 8) * 2, sKl + (size_t)r * CD + c8 * 8);
            }
        }
        CP_COMMIT();

        // ---- exp, denominators, masked P fragments -> gmem ----
        const bool store_p = (kt <= ktmax_store);
        #pragma unroll
        for (int u = 0; u < 4; u++) {
            const int cA = kt * 128 + kh * 64 + u * 16 + 2 * t;
            const int cB = cA + 8;
            float e00 = __expf(Sc[2*u][0] - SHIFT), e01 = __expf(Sc[2*u][1] - SHIFT);
            float e02 = __expf(Sc[2*u][2] - SHIFT), e03 = __expf(Sc[2*u][3] - SHIFT);
            float f00 = __expf(Sc[2*u+1][0] - SHIFT), f01 = __expf(Sc[2*u+1][1] - SHIFT);
            float f02 = __expf(Sc[2*u+1][2] - SHIFT), f03 = __expf(Sc[2*u+1][3] - SHIFT);
            d0 += (e00 + e01) + (f00 + f01);
            d1 += (e02 + e03) + (f02 + f03);
            if (store_p) {
                float p00 = (cA     < row0) ? e00 : 0.0f;
                float p01 = (cA + 1 < row0) ? e01 : 0.0f;
                float p02 = (cA     < row1) ? e02 : 0.0f;
                float p03 = (cA + 1 < row1) ? e03 : 0.0f;
                float q00 = (cB     < row0) ? f00 : 0.0f;
                float q01 = (cB + 1 < row0) ? f01 : 0.0f;
                float q02 = (cB     < row1) ? f02 : 0.0f;
                float q03 = (cB + 1 < row1) ? f03 : 0.0f;
                float h00 = __bfloat162float(__float2bfloat16(p00));
                float h01 = __bfloat162float(__float2bfloat16(p01));
                float h02 = __bfloat162float(__float2bfloat16(p02));
                float h03 = __bfloat162float(__float2bfloat16(p03));
                float i00 = __bfloat162float(__float2bfloat16(q00));
                float i01 = __bfloat162float(__float2bfloat16(q01));
                float i02 = __bfloat162float(__float2bfloat16(q02));
                float i03 = __bfloat162float(__float2bfloat16(q03));
                // fragment index: [b][qx][kt][rg][s = kh*4+u][lane]
                size_t fi = ((((((size_t)b * 16 + qx) * 8 + kt) * 4 + rg) * 8
                              + (kh * 4 + u)) * 32) + lane;
                g_Ph[fi] = make_uint4(pack2(h00, h01), pack2(h02, h03),
                                      pack2(i00, i01), pack2(i02, i03));
                g_Pl[fi] = make_uint4(pack2(p00 - h00, p01 - h01),
                                      pack2(p02 - h02, p03 - h03),
                                      pack2(q00 - i00, q01 - i01),
                                      pack2(q02 - i02, q03 - i03));
            }
        }

        CP_WAIT(0);                       // K(kt+1) landed
        __syncthreads();
    }

    // ---- denominators: quad reduce, cross-key-half combine, store ----
    d0 += __shfl_xor_sync(0xffffffffu, d0, 1);
    d0 += __shfl_xor_sync(0xffffffffu, d0, 2);
    d1 += __shfl_xor_sync(0xffffffffu, d1, 1);
    d1 += __shfl_xor_sync(0xffffffffu, d1, 2);
    float* dsm = (float*)(sm + S_ODS);
    if (t == 0) {
        dsm[kh * 64 + rg * 16 + g]     = d0;
        dsm[kh * 64 + rg * 16 + g + 8] = d1;
    }
    __syncthreads();
    if (tid < 64)
        g_d[(size_t)b * NSEQ + q0 + tid] = dsm[tid] + dsm[64 + tid];
}

// ---------------- kernel 3: O = P V (pure GEMM, wide warp tiles) ------------
// CTA = (b, qx, cm-half); 4 warps = 2 row-pairs x 2 cm-quarters; each warp
// does 32 rows x 64 cm, so V fragments are shared by only 2 warps (was 4).
__global__ __launch_bounds__(128, 3)
void pv_kernel(float* __restrict__ outg) {
    extern __shared__ uint8_t sm[];
    const uint32_t smb = smem_u32(sm);
    const int tid  = threadIdx.x;
    const int w    = tid >> 5, lane = tid & 31;
    const int rp   = w & 1;                        // row pair: rows rp*32..+31
    const int cmq  = w >> 1;                       // cm quarter within half
    const int g    = lane >> 2, t = lane & 3;

    // LPT decode: big qx first
    const int bid = blockIdx.x;                    // 0..1023
    const int qx  = 15 - (bid >> 6);
    const int r   = bid & 63;
    const int cmh = r & 1;                         // cm half
    const int b   = r >> 1;
    const int q0  = qx * 64;
    const int nch = ((qx >> 1) + 1) * 2;           // causal 64-key chunks

    const __nv_bfloat16* pVh = (const __nv_bfloat16*)g_Vth;
    const __nv_bfloat16* pVl = (const __nv_bfloat16*)g_Vtl;

    // stage one V chunk (128 cm rows x 64 keys, hi+lo) into buffer c&1
    auto stageV = [&](int c) {
        const __nv_bfloat16* sh = pVh + ((size_t)b * CMD + cmh * 128) * NSEQ + c * 64;
        const __nv_bfloat16* sl = pVl + ((size_t)b * CMD + cmh * 128) * NSEQ + c * 64;
        const uint32_t base = smb + (c & 1) * PV_BUF;
        #pragma unroll
        for (int it = 0; it < 8; it++) {
            int cc = tid + it * 128;               // 1024 granules per matrix
            int rr = cc >> 3, c8 = cc & 7;
            cpa16(base + ((uint32_t)rr * PVS + c8 * 8) * 2, sh + (size_t)rr * NSEQ + c8 * 8);
            cpa16(base + PV_MAT + ((uint32_t)rr * PVS + c8 * 8) * 2, sl + (size_t)rr * NSEQ + c8 * 8);
        }
    };

    // V ldsm per-lane base (within buffer): lanes<16 -> Vh, >=16 -> Vl,
    // offset to this warp's cm quarter.
    const uint32_t vn = lane & 7;
    const uint32_t vk = (lane & 8) ? 8 : 0;
    const uint32_t aVrel = ((lane < 16) ? 0u : (uint32_t)PV_MAT)
                         + ((uint32_t)cmq * 64 + vn) * (PVS * 2) + vk * 2;

    float O[2][8][4];
    #pragma unroll
    for (int i = 0; i < 2; i++)
        #pragma unroll
        for (int j = 0; j < 8; j++)
            #pragma unroll
            for (int x = 0; x < 4; x++) O[i][j][x] = 0.0f;

    // fragment base: [b][qx][kt][rg][s][lane]; strides kt:1024, rg:256, s:32
    const size_t fbase = ((((size_t)b * 16 + qx) * 8) * 4) * 8 * 32 + lane;
    const int rg0 = rp * 2;

    stageV(0);
    CP_COMMIT();

    for (int c = 0; c < nch; c++) {
        if (c + 1 < nch) {                         // prefetch next chunk
            stageV(c + 1);
            CP_COMMIT();
            CP_WAIT(1);                            // chunk c (oldest) landed
        } else {
            CP_WAIT(0);
        }
        __syncthreads();                           // chunk c visible everywhere

        const int kt = c >> 1;
        const int s0 = (c & 1) * 4;                // s range within kt
        const uint32_t vbase = smb + (c & 1) * PV_BUF + aVrel;
        #pragma unroll
        for (int s4 = 0; s4 < 4; s4++) {
            const size_t fi0 = fbase + (size_t)kt * 1024 + (size_t)rg0 * 256
                             + (size_t)(s0 + s4) * 32;
            uint4 Ph0 = g_Ph[fi0];                 // coalesced LDG.128
            uint4 Pl0 = g_Pl[fi0];
            uint4 Ph1 = g_Ph[fi0 + 256];
            uint4 Pl1 = g_Pl[fi0 + 256];
            #pragma unroll
            for (int j = 0; j < 8; j++) {
                uint32_t Bv[4];                    // [0,1]=Vh k0,k8  [2,3]=Vl
                ldsm4(Bv, vbase + (uint32_t)j * (8 * PVS * 2) + s4 * 32);
                mma16816(O[0][j], Ph0.x, Ph0.y, Ph0.z, Ph0.w, Bv[0], Bv[1]);
                mma16816(O[0][j], Pl0.x, Pl0.y, Pl0.z, Pl0.w, Bv[0], Bv[1]);
                mma16816(O[0][j], Ph0.x, Ph0.y, Ph0.z, Ph0.w, Bv[2], Bv[3]);
                mma16816(O[1][j], Ph1.x, Ph1.y, Ph1.z, Ph1.w, Bv[0], Bv[1]);
                mma16816(O[1][j], Pl1.x, Pl1.y, Pl1.z, Pl1.w, Bv[0], Bv[1]);
                mma16816(O[1][j], Ph1.x, Ph1.y, Ph1.z, Ph1.w, Bv[2], Bv[3]);
            }
        }
        __syncthreads();                           // done reading buffer c&1
    }

    // ---- epilogue: divide by full-row denominator, store ----
    #pragma unroll
    for (int rgi = 0; rgi < 2; rgi++) {
        const int rg = rg0 + rgi;
        const int row0 = q0 + rg * 16 + g;
        const int row1 = row0 + 8;
        const float i0 = 1.0f / g_d[(size_t)b * NSEQ + row0];
        const float i1 = 1.0f / g_d[(size_t)b * NSEQ + row1];
        const size_t r0o = ((size_t)b * NSEQ + row0) * CMD + cmh * 128 + cmq * 64;
        const size_t r1o = ((size_t)b * NSEQ + row1) * CMD + cmh * 128 + cmq * 64;
        #pragma unroll
        for (int j = 0; j < 8; j++) {
            float2 v0, v1;
            v0.x = O[rgi][j][0] * i0; v0.y = O[rgi][j][1] * i0;
            v1.x = O[rgi][j][2] * i1; v1.y = O[rgi][j][3] * i1;
            *(float2*)(outg + r0o + 8 * j + 2 * t) = v0;
            *(float2*)(outg + r1o + 8 * j + 2 * t) = v1;
        }
    }
}

// ---------------- launch ----------------
extern "C" void kernel_launch(void* const* d_in, const int* in_sizes, int n_in,
                              void* d_out, int out_size)
{
    const float* q = (const float*)d_in[0];
    const float* k = (const float*)d_in[1];
    const float* v = (const float*)d_in[2];
    float* out = (float*)d_out;

    cudaFuncSetAttribute(s_kernel,
                         cudaFuncAttributeMaxDynamicSharedMemorySize, S_SMEM);
    cudaFuncSetAttribute(pv_kernel,
                         cudaFuncAttributeMaxDynamicSharedMemorySize, PV_SMEM);

    prep_all<<<4096 + 8192, 256>>>(q, k, v);
    s_kernel<<<dim3(16, BATCH), 256, S_SMEM>>>();
    pv_kernel<<<1024, 128, PV_SMEM>>>(out);

    (void)in_sizes; (void)n_in; (void)out_size;
}